// round 1
// baseline (speedup 1.0000x reference)
#include <cuda_runtime.h>

// LSTM cell: z = x@W + h@R + b ; i,f,o = sigmoid, g = tanh ; c = f*c_ + i*g ; h = o*tanh(c)
// Sizes: B=8192, D=512, U=512, N=4U=2048.
// Stage 1: GEMM (M=8192, N=2048, K=1024 concatenated [x|h] @ [W;R]) -> g_z scratch.
// Stage 2: fused gate epilogue -> out = [h | h | c].

#define B_  8192
#define D_  512
#define U_  512
#define N_  2048
#define BM  128
#define BN  128
#define BK  16

// 64 MB scratch for pre-activation z (device global: allocation-free per harness rules)
__device__ float g_z[(size_t)B_ * N_];

__device__ __forceinline__ unsigned long long fma2(unsigned long long a,
                                                   unsigned long long b,
                                                   unsigned long long c) {
    unsigned long long d;
    asm("fma.rn.f32x2 %0, %1, %2, %3;" : "=l"(d) : "l"(a), "l"(b), "l"(c));
    return d;
}

__device__ __forceinline__ unsigned long long dup2(float x) {
    unsigned long long d;
    asm("mov.b64 %0, {%1, %1};" : "=l"(d) : "f"(x));
    return d;
}

__global__ __launch_bounds__(256)
void lstm_gemm(const float* __restrict__ X, const float* __restrict__ H,
               const float* __restrict__ W, const float* __restrict__ R)
{
    __shared__ __align__(16) float As[2][BK][BM];   // k-major (transposed A tile)
    __shared__ __align__(16) float Bs[2][BK][BN];

    const int tid = threadIdx.x;
    const int tx  = tid & 15;     // -> n (8 cols)
    const int ty  = tid >> 4;     // -> m (8 rows)
    const int bx  = blockIdx.x;   // n tile (16)
    const int by  = blockIdx.y;   // m tile (64)

    // global-load assignment
    const int ar = tid >> 1;        // 0..127: A row within tile
    const int ac = (tid & 1) * 8;   // k offset 0/8
    const int br = tid >> 4;        // 0..15 : B k-row
    const int bc = (tid & 15) * 8;  // n offset

    const int m0g = by * BM;
    const int n0g = bx * BN;

    unsigned long long acc[4][8];   // acc[p][j]: rows (2p,2p+1) packed, col j
    #pragma unroll
    for (int p = 0; p < 4; ++p)
        #pragma unroll
        for (int j = 0; j < 8; ++j) acc[p][j] = 0ull;

    const int NT = 64;  // 2 phases (x@W, h@R) * 32 k-tiles

    float4 a0, a1, b0, b1;

    auto ldgTile = [&](int t) {
        const float* Ap = (t < 32) ? X : H;
        const float* Bp = (t < 32) ? W : R;
        const int kb = (t & 31) * BK;
        const float* ap = Ap + (size_t)(m0g + ar) * D_ + kb + ac;
        a0 = *(const float4*)(ap);
        a1 = *(const float4*)(ap + 4);
        const float* bp = Bp + (size_t)(kb + br) * N_ + n0g + bc;
        b0 = *(const float4*)(bp);
        b1 = *(const float4*)(bp + 4);
    };
    auto stsTile = [&](int buf) {
        As[buf][ac + 0][ar] = a0.x; As[buf][ac + 1][ar] = a0.y;
        As[buf][ac + 2][ar] = a0.z; As[buf][ac + 3][ar] = a0.w;
        As[buf][ac + 4][ar] = a1.x; As[buf][ac + 5][ar] = a1.y;
        As[buf][ac + 6][ar] = a1.z; As[buf][ac + 7][ar] = a1.w;
        *(float4*)&Bs[buf][br][bc]     = b0;
        *(float4*)&Bs[buf][br][bc + 4] = b1;
    };

    ldgTile(0);
    stsTile(0);
    __syncthreads();

    for (int t = 0; t < NT; ++t) {
        const int cur = t & 1;
        if (t + 1 < NT) ldgTile(t + 1);

        #pragma unroll
        for (int k = 0; k < BK; ++k) {
            const ulonglong2* apair = (const ulonglong2*)&As[cur][k][ty * 8];
            ulonglong2 a01 = apair[0];   // rows 0-1, 2-3 (packed pairs)
            ulonglong2 a23 = apair[1];   // rows 4-5, 6-7
            const float4* bp4 = (const float4*)&Bs[cur][k][tx * 8];
            float4 bb0 = bp4[0], bb1 = bp4[1];
            unsigned long long bd[8];
            bd[0] = dup2(bb0.x); bd[1] = dup2(bb0.y);
            bd[2] = dup2(bb0.z); bd[3] = dup2(bb0.w);
            bd[4] = dup2(bb1.x); bd[5] = dup2(bb1.y);
            bd[6] = dup2(bb1.z); bd[7] = dup2(bb1.w);
            #pragma unroll
            for (int j = 0; j < 8; ++j) {
                acc[0][j] = fma2(a01.x, bd[j], acc[0][j]);
                acc[1][j] = fma2(a01.y, bd[j], acc[1][j]);
                acc[2][j] = fma2(a23.x, bd[j], acc[2][j]);
                acc[3][j] = fma2(a23.y, bd[j], acc[3][j]);
            }
        }

        if (t + 1 < NT) stsTile((t + 1) & 1);
        __syncthreads();
    }

    // write z tile
    const int m0 = m0g + ty * 8;
    const int n0 = n0g + tx * 8;
    #pragma unroll
    for (int p = 0; p < 4; ++p) {
        float lo[8], hi[8];
        #pragma unroll
        for (int j = 0; j < 8; ++j) {
            unsigned int l, h;
            asm("mov.b64 {%0, %1}, %2;" : "=r"(l), "=r"(h) : "l"(acc[p][j]));
            lo[j] = __uint_as_float(l);
            hi[j] = __uint_as_float(h);
        }
        float* z0 = g_z + (size_t)(m0 + 2 * p) * N_ + n0;
        float* z1 = z0 + N_;
        *(float4*)(z0)     = make_float4(lo[0], lo[1], lo[2], lo[3]);
        *(float4*)(z0 + 4) = make_float4(lo[4], lo[5], lo[6], lo[7]);
        *(float4*)(z1)     = make_float4(hi[0], hi[1], hi[2], hi[3]);
        *(float4*)(z1 + 4) = make_float4(hi[4], hi[5], hi[6], hi[7]);
    }
}

__device__ __forceinline__ float sigf(float x) {
    return 1.0f / (1.0f + expf(-x));
}

__global__ __launch_bounds__(256)
void lstm_epilogue(const float* __restrict__ C,
                   const float* __restrict__ bias,
                   float* __restrict__ out)
{
    const int total4 = B_ * U_ / 4;
    int idx4 = blockIdx.x * blockDim.x + threadIdx.x;
    if (idx4 >= total4) return;

    const int b  = idx4 / (U_ / 4);
    const int u4 = (idx4 % (U_ / 4)) * 4;

    const float* zr = g_z + (size_t)b * N_;
    float4 zi = *(const float4*)(zr + u4);
    float4 zf = *(const float4*)(zr + 512  + u4);
    float4 zg = *(const float4*)(zr + 1024 + u4);
    float4 zo = *(const float4*)(zr + 1536 + u4);
    float4 bi = *(const float4*)(bias + u4);
    float4 bf = *(const float4*)(bias + 512  + u4);
    float4 bg = *(const float4*)(bias + 1024 + u4);
    float4 bo = *(const float4*)(bias + 1536 + u4);
    float4 cv = *(const float4*)(C + (size_t)b * U_ + u4);

    const float* pzi = (const float*)&zi; const float* pbi = (const float*)&bi;
    const float* pzf = (const float*)&zf; const float* pbf = (const float*)&bf;
    const float* pzg = (const float*)&zg; const float* pbg = (const float*)&bg;
    const float* pzo = (const float*)&zo; const float* pbo = (const float*)&bo;
    const float* pc  = (const float*)&cv;

    float4 hv, cnv;
    float* ph = (float*)&hv;
    float* pcn = (float*)&cnv;

    #pragma unroll
    for (int l = 0; l < 4; ++l) {
        float iv = sigf(pzi[l] + pbi[l]);
        float fv = sigf(pzf[l] + pbf[l]);
        float gv = tanhf(pzg[l] + pbg[l]);
        float ov = sigf(pzo[l] + pbo[l]);
        float cn = fv * pc[l] + iv * gv;
        ph[l]  = ov * tanhf(cn);
        pcn[l] = cn;
    }

    const size_t BU = (size_t)B_ * U_;
    const size_t off = (size_t)b * U_ + u4;
    *(float4*)(out + off)          = hv;   // h
    *(float4*)(out + BU + off)     = hv;   // h (duplicate output)
    *(float4*)(out + 2 * BU + off) = cnv;  // c
}

extern "C" void kernel_launch(void* const* d_in, const int* in_sizes, int n_in,
                              void* d_out, int out_size)
{
    const float* X    = (const float*)d_in[0];  // inputs [B, D]
    const float* H    = (const float*)d_in[1];  // h_tm1  [B, U]
    const float* C    = (const float*)d_in[2];  // c_tm1  [B, U]
    const float* W    = (const float*)d_in[3];  // kernel [D, 4U]
    const float* R    = (const float*)d_in[4];  // recurrent_kernel [U, 4U]
    const float* bias = (const float*)d_in[5];  // bias [4U]
    float* out = (float*)d_out;

    dim3 ggrid(N_ / BN, B_ / BM);   // (16, 64)
    lstm_gemm<<<ggrid, 256>>>(X, H, W, R);

    const int total4 = B_ * U_ / 4;
    lstm_epilogue<<<(total4 + 255) / 256, 256>>>(C, bias, out);
}

// round 3
// speedup vs baseline: 1.9769x; 1.9769x over previous
#include <cuda_runtime.h>
#include <cuda_bf16.h>
#include <cstdint>

// LSTM cell: bf16 split-precision GEMM via mma.sync (baseline PTX, works on
// compute_103 target) + fused gate epilogue.
// z = [X|H] @ [W;R] (+bias); gates i,f,g,o -> c,h; out = [h | h | c].
// B columns permuted at conversion: col' = 4*u + gate, so a BN=128 tile holds
// 32 complete gate quadruples.

#define MB   8192
#define KK   1024
#define NTOT 2048
#define UU   512
#define BM   128
#define BN   128
#define BK   32
#define KT   (KK / BK)          // 32 k-iterations
#define ROWB 80                 // smem row stride bytes (64B data + 16 pad)
#define TILEB (128 * ROWB)      // 10240 per [128 x BK] bf16 tile
#define STAGEB (4 * TILEB)      // Ah, Al, Bh, Bl
#define SMEM_DYN (2 * STAGEB)   // 81920; z-stage (128*132*4=67584) reuses it

// -------- device scratch --------
__device__ __nv_bfloat16 g_Ah[(size_t)MB * KK];
__device__ __nv_bfloat16 g_Al[(size_t)MB * KK];
__device__ __nv_bfloat16 g_Bh[(size_t)NTOT * KK];
__device__ __nv_bfloat16 g_Bl[(size_t)NTOT * KK];

// -------- helpers --------
__device__ __forceinline__ uint32_t s2u(const void* p) {
    uint32_t a;
    asm("{ .reg .u64 t; cvta.to.shared.u64 t, %1; cvt.u32.u64 %0, t; }"
        : "=r"(a) : "l"(p));
    return a;
}
__device__ __forceinline__ void cp16(uint32_t dst, const void* src) {
    asm volatile("cp.async.cg.shared.global [%0], [%1], 16;"
                 :: "r"(dst), "l"((unsigned long long)__cvta_generic_to_global(src))
                 : "memory");
}
#define CP_COMMIT() asm volatile("cp.async.commit_group;" ::: "memory")
#define CP_WAIT1()  asm volatile("cp.async.wait_group 1;" ::: "memory")

__device__ __forceinline__ void ldsm4(uint32_t* r, uint32_t addr) {
    asm volatile("ldmatrix.sync.aligned.m8n8.x4.shared.b16 {%0,%1,%2,%3}, [%4];"
                 : "=r"(r[0]), "=r"(r[1]), "=r"(r[2]), "=r"(r[3]) : "r"(addr));
}
__device__ __forceinline__ void mma16816(float* d, const uint32_t* a,
                                         const uint32_t* b) {
    asm volatile(
        "mma.sync.aligned.m16n8k16.row.col.f32.bf16.bf16.f32 "
        "{%0,%1,%2,%3}, {%4,%5,%6,%7}, {%8,%9}, {%0,%1,%2,%3};"
        : "+f"(d[0]), "+f"(d[1]), "+f"(d[2]), "+f"(d[3])
        : "r"(a[0]), "r"(a[1]), "r"(a[2]), "r"(a[3]), "r"(b[0]), "r"(b[1]));
}
__device__ __forceinline__ float sigf(float x) { return 1.0f / (1.0f + expf(-x)); }
__device__ __forceinline__ void split_bf16(float v, __nv_bfloat16& h, __nv_bfloat16& l) {
    h = __float2bfloat16(v);
    l = __float2bfloat16(v - __bfloat162float(h));
}

// -------- conversion kernels --------
__global__ __launch_bounds__(256)
void conv_a(const float* __restrict__ X, const float* __restrict__ H)
{
    int idx = blockIdx.x * 256 + threadIdx.x;   // quad index
    int row = idx >> 8;
    int c4  = (idx & 255) * 4;
    float4 v = (c4 < 512)
        ? ((const float4*)X)[(size_t)row * 128 + (c4 >> 2)]
        : ((const float4*)H)[(size_t)row * 128 + ((c4 - 512) >> 2)];
    __nv_bfloat16 h[4], l[4];
    split_bf16(v.x, h[0], l[0]); split_bf16(v.y, h[1], l[1]);
    split_bf16(v.z, h[2], l[2]); split_bf16(v.w, h[3], l[3]);
    ((uint2*)g_Ah)[idx] = *(uint2*)h;
    ((uint2*)g_Al)[idx] = *(uint2*)l;
}

__global__ __launch_bounds__(256)
void conv_b(const float* __restrict__ W, const float* __restrict__ R)
{
    int colp = blockIdx.x;                 // permuted column 0..2047
    int u    = colp >> 2;
    int gate = colp & 3;
    int zcol = gate * 512 + u;
    int k0   = threadIdx.x * 4;
    float v[4];
    #pragma unroll
    for (int j = 0; j < 4; ++j) {
        int k = k0 + j;
        v[j] = (k < 512) ? W[(size_t)k * NTOT + zcol]
                         : R[(size_t)(k - 512) * NTOT + zcol];
    }
    __nv_bfloat16 h[4], l[4];
    #pragma unroll
    for (int j = 0; j < 4; ++j) split_bf16(v[j], h[j], l[j]);
    size_t q = (size_t)colp * 256 + threadIdx.x;
    ((uint2*)g_Bh)[q] = *(uint2*)h;
    ((uint2*)g_Bl)[q] = *(uint2*)l;
}

// -------- fused GEMM + gates --------
__global__ __launch_bounds__(256, 1)
void lstm_mma(const float* __restrict__ Cprev,
              const float* __restrict__ bias,
              float* __restrict__ out)
{
    extern __shared__ __align__(128) char smem[];
    const uint32_t sm = s2u(smem);
    const int tid = threadIdx.x, wid = tid >> 5, lane = tid & 31;
    const int warp_m = wid >> 2;            // 0..1  (64 rows each)
    const int warp_n = wid & 3;             // 0..3  (32 cols each)
    const int m0 = blockIdx.y * BM;
    const int n0 = blockIdx.x * BN;

    float acc[4][4][4];
    #pragma unroll
    for (int mi = 0; mi < 4; ++mi)
        #pragma unroll
        for (int ni = 0; ni < 4; ++ni)
            #pragma unroll
            for (int r = 0; r < 4; ++r) acc[mi][ni][r] = 0.0f;

    // stage offsets
    auto load_stage = [&](int t, int stg) {
        const uint32_t sb = sm + stg * STAGEB;
        const int kb = t * BK;
        #pragma unroll
        for (int j = 0; j < 2; ++j) {
            int i = tid + j * 256;          // 0..511
            int r = i >> 2, seg = i & 3;
            uint32_t dst = sb + r * ROWB + seg * 16;
            size_t goA = (size_t)(m0 + r) * KK + kb + seg * 8;
            cp16(dst,             g_Ah + goA);
            cp16(dst + TILEB,     g_Al + goA);
            size_t goB = (size_t)(n0 + r) * KK + kb + seg * 8;
            cp16(dst + 2 * TILEB, g_Bh + goB);
            cp16(dst + 3 * TILEB, g_Bl + goB);
        }
    };

    load_stage(0, 0); CP_COMMIT();
    load_stage(1, 1); CP_COMMIT();

    for (int t = 0; t < KT; ++t) {
        const int stg = t & 1;
        CP_WAIT1();
        __syncthreads();

        const uint32_t sb = sm + stg * STAGEB;
        #pragma unroll
        for (int ks = 0; ks < 2; ++ks) {
            const uint32_t kB = ks * 32;    // 16 bf16 = 32 bytes
            uint32_t ah[4][4], al[4][4], bh[2][4], bl[2][4];
            #pragma unroll
            for (int mi = 0; mi < 4; ++mi) {
                uint32_t a = sb + (warp_m * 64 + mi * 16 + (lane & 15)) * ROWB
                           + kB + ((lane >> 4) << 4);
                ldsm4(ah[mi], a);
                ldsm4(al[mi], a + TILEB);
            }
            #pragma unroll
            for (int nj = 0; nj < 2; ++nj) {
                uint32_t a = sb + 2 * TILEB
                           + (warp_n * 32 + nj * 16 + (lane & 7) + ((lane & 16) >> 1)) * ROWB
                           + kB + ((lane & 8) << 1);
                ldsm4(bh[nj], a);
                ldsm4(bl[nj], a + TILEB);
            }
            // pass 1: Ah * Bh
            #pragma unroll
            for (int mi = 0; mi < 4; ++mi)
                #pragma unroll
                for (int ni = 0; ni < 4; ++ni)
                    mma16816(acc[mi][ni], ah[mi], &bh[ni >> 1][(ni & 1) * 2]);
            // pass 2: Ah * Bl
            #pragma unroll
            for (int mi = 0; mi < 4; ++mi)
                #pragma unroll
                for (int ni = 0; ni < 4; ++ni)
                    mma16816(acc[mi][ni], ah[mi], &bl[ni >> 1][(ni & 1) * 2]);
            // pass 3: Al * Bh
            #pragma unroll
            for (int mi = 0; mi < 4; ++mi)
                #pragma unroll
                for (int ni = 0; ni < 4; ++ni)
                    mma16816(acc[mi][ni], al[mi], &bh[ni >> 1][(ni & 1) * 2]);
        }

        __syncthreads();
        if (t + 2 < KT) {
            load_stage(t + 2, stg);
            CP_COMMIT();
        }
    }

    // ---- epilogue: stage z through smem (operand buffers are dead) ----
    float* zs = (float*)smem;               // [128][132]
    const int g = lane >> 2, c2 = (lane & 3) * 2;
    #pragma unroll
    for (int mi = 0; mi < 4; ++mi) {
        const int r0 = warp_m * 64 + mi * 16 + g;
        #pragma unroll
        for (int ni = 0; ni < 4; ++ni) {
            const int col = warp_n * 32 + ni * 8 + c2;
            zs[r0 * 132 + col]           = acc[mi][ni][0];
            zs[r0 * 132 + col + 1]       = acc[mi][ni][1];
            zs[(r0 + 8) * 132 + col]     = acc[mi][ni][2];
            zs[(r0 + 8) * 132 + col + 1] = acc[mi][ni][3];
        }
    }
    __syncthreads();

    const size_t BU = (size_t)MB * UU;
    #pragma unroll
    for (int i = 0; i < 16; ++i) {
        int q   = tid + i * 256;            // 0..4095
        int row = q >> 5;
        int ul  = q & 31;
        float4 zq = *(float4*)&zs[row * 132 + ul * 4];
        int u = blockIdx.x * 32 + ul;
        float zi = zq.x + __ldg(bias + u);
        float zf = zq.y + __ldg(bias + 512 + u);
        float zg = zq.z + __ldg(bias + 1024 + u);
        float zo = zq.w + __ldg(bias + 1536 + u);
        float cp = Cprev[(size_t)(m0 + row) * UU + u];
        float cn = sigf(zf) * cp + sigf(zi) * tanhf(zg);
        float hv = sigf(zo) * tanhf(cn);
        size_t o = (size_t)(m0 + row) * UU + u;
        out[o]          = hv;
        out[o + BU]     = hv;
        out[o + 2 * BU] = cn;
    }
}

// -------- launch --------
extern "C" void kernel_launch(void* const* d_in, const int* in_sizes, int n_in,
                              void* d_out, int out_size)
{
    const float* X    = (const float*)d_in[0];
    const float* H    = (const float*)d_in[1];
    const float* C    = (const float*)d_in[2];
    const float* W    = (const float*)d_in[3];
    const float* R    = (const float*)d_in[4];
    const float* bias = (const float*)d_in[5];
    float* out = (float*)d_out;

    static bool attr_done = false;
    if (!attr_done) {
        cudaFuncSetAttribute(lstm_mma,
                             cudaFuncAttributeMaxDynamicSharedMemorySize, SMEM_DYN);
        attr_done = true;
    }

    conv_a<<<MB * KK / 4 / 256, 256>>>(X, H);
    conv_b<<<NTOT, 256>>>(W, R);

    dim3 grid(NTOT / BN, MB / BM);          // (16, 64)
    lstm_mma<<<grid, 256, SMEM_DYN>>>(C, bias, out);
}

// round 4
// speedup vs baseline: 3.7296x; 1.8866x over previous
#include <cuda_runtime.h>
#include <cuda_fp16.h>
#include <cstdint>

// LSTM cell: fp16 split-precision GEMM (2 passes: Ah*Bh + Al*Bh) via mma.sync
// + fused gate epilogue. z = [X|H] @ [W;R] (+bias); out = [h | h | c].
// B columns permuted: col' = 4*u + gate -> BN=128 tile holds 32 gate quads.

#define MB   8192
#define KK   1024
#define NTOT 2048
#define UU   512
#define BM   128
#define BN   128
#define BK   32
#define KT   (KK / BK)              // 32 k-iterations
#define ROWB 80                     // smem row stride bytes (64B data + 16 pad)
#define TILEB (128 * ROWB)          // 10240 per [128 x 32] fp16 tile
#define STAGEB (3 * TILEB)          // Ah, Al, Bh
#define NSTG 3
#define SMEM_DYN (NSTG * STAGEB)    // 92160; epilogue z-stage (67584) reuses it

// -------- device scratch --------
__device__ __half g_Ah[(size_t)MB * KK];
__device__ __half g_Al[(size_t)MB * KK];
__device__ __half g_Bh[(size_t)NTOT * KK];

// -------- helpers --------
__device__ __forceinline__ uint32_t s2u(const void* p) {
    uint32_t a;
    asm("{ .reg .u64 t; cvta.to.shared.u64 t, %1; cvt.u32.u64 %0, t; }"
        : "=r"(a) : "l"(p));
    return a;
}
__device__ __forceinline__ void cp16(uint32_t dst, const void* src) {
    asm volatile("cp.async.cg.shared.global [%0], [%1], 16;"
                 :: "r"(dst), "l"((unsigned long long)__cvta_generic_to_global(src))
                 : "memory");
}
#define CP_COMMIT() asm volatile("cp.async.commit_group;" ::: "memory")
#define CP_WAIT1()  asm volatile("cp.async.wait_group 1;" ::: "memory")

__device__ __forceinline__ void ldsm4(uint32_t* r, uint32_t addr) {
    asm volatile("ldmatrix.sync.aligned.m8n8.x4.shared.b16 {%0,%1,%2,%3}, [%4];"
                 : "=r"(r[0]), "=r"(r[1]), "=r"(r[2]), "=r"(r[3]) : "r"(addr));
}
__device__ __forceinline__ void mma16816(float* d, const uint32_t* a,
                                         const uint32_t* b) {
    asm volatile(
        "mma.sync.aligned.m16n8k16.row.col.f32.f16.f16.f32 "
        "{%0,%1,%2,%3}, {%4,%5,%6,%7}, {%8,%9}, {%0,%1,%2,%3};"
        : "+f"(d[0]), "+f"(d[1]), "+f"(d[2]), "+f"(d[3])
        : "r"(a[0]), "r"(a[1]), "r"(a[2]), "r"(a[3]), "r"(b[0]), "r"(b[1]));
}
__device__ __forceinline__ float ex2f(float x) {
    float y; asm("ex2.approx.f32 %0, %1;" : "=f"(y) : "f"(x)); return y;
}
__device__ __forceinline__ float rcpf(float x) {
    float y; asm("rcp.approx.f32 %0, %1;" : "=f"(y) : "f"(x)); return y;
}
__device__ __forceinline__ float sigf(float x) {
    return rcpf(1.0f + ex2f(-1.4426950408889634f * x));
}
__device__ __forceinline__ float tanhf_fast(float x) {
    return 1.0f - 2.0f * rcpf(1.0f + ex2f(2.8853900817779268f * x));
}
__device__ __forceinline__ void split_h(float v, __half& h, __half& l) {
    h = __float2half(v);
    l = __float2half(v - __half2float(h));
}

// -------- conversion kernels --------
__global__ __launch_bounds__(256)
void conv_a(const float* __restrict__ X, const float* __restrict__ H)
{
    int idx = blockIdx.x * 256 + threadIdx.x;   // quad index
    int row = idx >> 8;
    int c4  = (idx & 255) * 4;
    float4 v = (c4 < 512)
        ? ((const float4*)X)[(size_t)row * 128 + (c4 >> 2)]
        : ((const float4*)H)[(size_t)row * 128 + ((c4 - 512) >> 2)];
    __half h[4], l[4];
    split_h(v.x, h[0], l[0]); split_h(v.y, h[1], l[1]);
    split_h(v.z, h[2], l[2]); split_h(v.w, h[3], l[3]);
    ((uint2*)g_Ah)[idx] = *(uint2*)h;
    ((uint2*)g_Al)[idx] = *(uint2*)l;
}

__global__ __launch_bounds__(256)
void conv_b(const float* __restrict__ W, const float* __restrict__ R)
{
    int colp = blockIdx.x;                 // permuted column 0..2047
    int u    = colp >> 2;
    int gate = colp & 3;
    int zcol = gate * 512 + u;
    int k0   = threadIdx.x * 4;
    float v[4];
    #pragma unroll
    for (int j = 0; j < 4; ++j) {
        int k = k0 + j;
        v[j] = (k < 512) ? W[(size_t)k * NTOT + zcol]
                         : R[(size_t)(k - 512) * NTOT + zcol];
    }
    __half h[4];
    #pragma unroll
    for (int j = 0; j < 4; ++j) h[j] = __float2half(v[j]);
    ((uint2*)g_Bh)[(size_t)colp * 256 + threadIdx.x] = *(uint2*)h;
}

// -------- fused GEMM + gates --------
__global__ __launch_bounds__(256, 2)
void lstm_mma(const float* __restrict__ Cprev,
              const float* __restrict__ bias,
              float* __restrict__ out)
{
    extern __shared__ __align__(128) char smem[];
    const uint32_t sm = s2u(smem);
    const int tid = threadIdx.x, wid = tid >> 5, lane = tid & 31;
    const int warp_m = wid >> 2;            // 0..1  (64 rows)
    const int warp_n = wid & 3;             // 0..3  (32 cols)
    const int m0 = blockIdx.y * BM;
    const int n0 = blockIdx.x * BN;

    float acc[4][4][4];
    #pragma unroll
    for (int mi = 0; mi < 4; ++mi)
        #pragma unroll
        for (int ni = 0; ni < 4; ++ni)
            #pragma unroll
            for (int r = 0; r < 4; ++r) acc[mi][ni][r] = 0.0f;

    // per-thread load coords (same for all 3 tiles): 2 rows x 1 seg each j
    const int lr0 = tid >> 2, lseg = tid & 3;

    auto load_stage = [&](int t, int stg) {
        const uint32_t sb = sm + stg * STAGEB;
        const int kb = t * BK;
        #pragma unroll
        for (int j = 0; j < 2; ++j) {
            int r = lr0 + j * 64;
            uint32_t dst = sb + r * ROWB + lseg * 16;
            size_t goA = (size_t)(m0 + r) * KK + kb + lseg * 8;
            cp16(dst,             g_Ah + goA);
            cp16(dst + TILEB,     g_Al + goA);
            cp16(dst + 2 * TILEB, g_Bh + (size_t)(n0 + r) * KK + kb + lseg * 8);
        }
    };

    load_stage(0, 0); CP_COMMIT();
    load_stage(1, 1); CP_COMMIT();

    // precomputed ldsm sub-addresses (relative to stage base)
    const uint32_t aoff = (warp_m * 64 + (lane & 15)) * ROWB + ((lane >> 4) << 4);
    const uint32_t boff = 2 * TILEB
        + (warp_n * 32 + (lane & 7) + ((lane & 16) >> 1)) * ROWB + ((lane & 8) << 1);

    for (int t = 0; t < KT; ++t) {
        CP_WAIT1();
        __syncthreads();

        const uint32_t sb = sm + (t % NSTG) * STAGEB;
        #pragma unroll
        for (int ks = 0; ks < 2; ++ks) {
            const uint32_t kB = ks * 32;
            uint32_t ah[4][4], al[4][4], bh[2][4];
            #pragma unroll
            for (int mi = 0; mi < 4; ++mi) {
                uint32_t a = sb + aoff + mi * (16 * ROWB) + kB;
                ldsm4(ah[mi], a);
                ldsm4(al[mi], a + TILEB);
            }
            #pragma unroll
            for (int nj = 0; nj < 2; ++nj)
                ldsm4(bh[nj], sb + boff + nj * (16 * ROWB) + kB);

            #pragma unroll
            for (int mi = 0; mi < 4; ++mi)
                #pragma unroll
                for (int ni = 0; ni < 4; ++ni)
                    mma16816(acc[mi][ni], ah[mi], &bh[ni >> 1][(ni & 1) * 2]);
            #pragma unroll
            for (int mi = 0; mi < 4; ++mi)
                #pragma unroll
                for (int ni = 0; ni < 4; ++ni)
                    mma16816(acc[mi][ni], al[mi], &bh[ni >> 1][(ni & 1) * 2]);
        }

        if (t + 2 < KT) load_stage(t + 2, (t + 2) % NSTG);
        CP_COMMIT();
    }

    // ---- epilogue: stage z through smem (operand buffers dead) ----
    __syncthreads();
    float* zs = (float*)smem;               // [128][132]
    const int g = lane >> 2, c2 = (lane & 3) * 2;
    #pragma unroll
    for (int mi = 0; mi < 4; ++mi) {
        const int r0 = warp_m * 64 + mi * 16 + g;
        #pragma unroll
        for (int ni = 0; ni < 4; ++ni) {
            const int col = warp_n * 32 + ni * 8 + c2;
            zs[r0 * 132 + col]           = acc[mi][ni][0];
            zs[r0 * 132 + col + 1]       = acc[mi][ni][1];
            zs[(r0 + 8) * 132 + col]     = acc[mi][ni][2];
            zs[(r0 + 8) * 132 + col + 1] = acc[mi][ni][3];
        }
    }
    __syncthreads();

    const size_t BU = (size_t)MB * UU;
    #pragma unroll
    for (int i = 0; i < 16; ++i) {
        int q   = tid + i * 256;            // 0..4095
        int row = q >> 5;
        int ul  = q & 31;
        float4 zq = *(float4*)&zs[row * 132 + ul * 4];
        int u = blockIdx.x * 32 + ul;
        float zi = zq.x + __ldg(bias + u);
        float zf = zq.y + __ldg(bias + 512 + u);
        float zg = zq.z + __ldg(bias + 1024 + u);
        float zo = zq.w + __ldg(bias + 1536 + u);
        float cp = Cprev[(size_t)(m0 + row) * UU + u];
        float cn = sigf(zf) * cp + sigf(zi) * tanhf_fast(zg);
        float hv = sigf(zo) * tanhf_fast(cn);
        size_t o = (size_t)(m0 + row) * UU + u;
        out[o]          = hv;
        out[o + BU]     = hv;
        out[o + 2 * BU] = cn;
    }
}

// -------- launch --------
extern "C" void kernel_launch(void* const* d_in, const int* in_sizes, int n_in,
                              void* d_out, int out_size)
{
    const float* X    = (const float*)d_in[0];
    const float* H    = (const float*)d_in[1];
    const float* C    = (const float*)d_in[2];
    const float* W    = (const float*)d_in[3];
    const float* R    = (const float*)d_in[4];
    const float* bias = (const float*)d_in[5];
    float* out = (float*)d_out;

    static bool attr_done = false;
    if (!attr_done) {
        cudaFuncSetAttribute(lstm_mma,
                             cudaFuncAttributeMaxDynamicSharedMemorySize, SMEM_DYN);
        attr_done = true;
    }

    conv_a<<<MB * KK / 4 / 256, 256>>>(X, H);
    conv_b<<<NTOT, 256>>>(W, R);

    dim3 grid(NTOT / BN, MB / BM);          // (16, 64)
    lstm_mma<<<grid, 256, SMEM_DYN>>>(C, bias, out);
}

// round 5
// speedup vs baseline: 5.8724x; 1.5745x over previous
#include <cuda_runtime.h>
#include <cuda_fp16.h>
#include <cstdint>

// LSTM cell: single-pass fp16 GEMM via mma.sync + fused gate epilogue.
// z = [X|H] @ [W;R] (+bias); gates i,f,g,o -> c,h; out = [h | h | c].
// B columns permuted: col' = 4*u + gate -> BN=128 tile holds 32 gate quads.
// Precision: A,B rounded to fp16 (rel_err ~3-4e-4, threshold 1e-3).

#define MB   8192
#define KK   1024
#define NTOT 2048
#define UU   512
#define BM   128
#define BN   128
#define BK   32
#define KT   (KK / BK)              // 32 k-iterations
#define ROWB 80                     // smem row stride bytes (64B data + 16 pad)
#define TILEB (128 * ROWB)          // 10240 per [128 x 32] fp16 tile
#define STAGEB (2 * TILEB)          // A, B
#define NSTG 4
#define SMEM_DYN (NSTG * STAGEB)    // 81920; epilogue z-stage (67584) reuses it

// -------- device scratch --------
__device__ __half g_A[(size_t)MB * KK];
__device__ __half g_B[(size_t)NTOT * KK];

// -------- helpers --------
__device__ __forceinline__ uint32_t s2u(const void* p) {
    uint32_t a;
    asm("{ .reg .u64 t; cvta.to.shared.u64 t, %1; cvt.u32.u64 %0, t; }"
        : "=r"(a) : "l"(p));
    return a;
}
__device__ __forceinline__ void cp16(uint32_t dst, const void* src) {
    asm volatile("cp.async.cg.shared.global [%0], [%1], 16;"
                 :: "r"(dst), "l"((unsigned long long)__cvta_generic_to_global(src))
                 : "memory");
}
#define CP_COMMIT() asm volatile("cp.async.commit_group;" ::: "memory")
#define CP_WAIT2()  asm volatile("cp.async.wait_group 2;" ::: "memory")

__device__ __forceinline__ void ldsm4(uint32_t* r, uint32_t addr) {
    asm volatile("ldmatrix.sync.aligned.m8n8.x4.shared.b16 {%0,%1,%2,%3}, [%4];"
                 : "=r"(r[0]), "=r"(r[1]), "=r"(r[2]), "=r"(r[3]) : "r"(addr));
}
__device__ __forceinline__ void mma16816(float* d, const uint32_t* a,
                                         const uint32_t* b) {
    asm volatile(
        "mma.sync.aligned.m16n8k16.row.col.f32.f16.f16.f32 "
        "{%0,%1,%2,%3}, {%4,%5,%6,%7}, {%8,%9}, {%0,%1,%2,%3};"
        : "+f"(d[0]), "+f"(d[1]), "+f"(d[2]), "+f"(d[3])
        : "r"(a[0]), "r"(a[1]), "r"(a[2]), "r"(a[3]), "r"(b[0]), "r"(b[1]));
}
__device__ __forceinline__ float ex2f(float x) {
    float y; asm("ex2.approx.f32 %0, %1;" : "=f"(y) : "f"(x)); return y;
}
__device__ __forceinline__ float rcpf(float x) {
    float y; asm("rcp.approx.f32 %0, %1;" : "=f"(y) : "f"(x)); return y;
}
__device__ __forceinline__ float sigf(float x) {
    return rcpf(1.0f + ex2f(-1.4426950408889634f * x));
}
__device__ __forceinline__ float tanhf_fast(float x) {
    return 1.0f - 2.0f * rcpf(1.0f + ex2f(2.8853900817779268f * x));
}

// -------- conversion kernels --------
__global__ __launch_bounds__(256)
void conv_a(const float* __restrict__ X, const float* __restrict__ H)
{
    int idx = blockIdx.x * 256 + threadIdx.x;   // oct index (8 elems), 1M total
    int row = idx >> 7;
    int c8  = (idx & 127) * 8;
    const float4* src = (c8 < 512)
        ? (const float4*)(X + (size_t)row * 512 + c8)
        : (const float4*)(H + (size_t)row * 512 + (c8 - 512));
    float4 v0 = src[0], v1 = src[1];
    __half h[8];
    h[0] = __float2half(v0.x); h[1] = __float2half(v0.y);
    h[2] = __float2half(v0.z); h[3] = __float2half(v0.w);
    h[4] = __float2half(v1.x); h[5] = __float2half(v1.y);
    h[6] = __float2half(v1.z); h[7] = __float2half(v1.w);
    ((uint4*)g_A)[idx] = *(uint4*)h;
}

__global__ __launch_bounds__(256)
void conv_b(const float* __restrict__ W, const float* __restrict__ R)
{
    int colp = blockIdx.x;                 // permuted column 0..2047
    int u    = colp >> 2;
    int gate = colp & 3;
    int zcol = gate * 512 + u;
    int k0   = threadIdx.x * 4;
    float v[4];
    #pragma unroll
    for (int j = 0; j < 4; ++j) {
        int k = k0 + j;
        v[j] = (k < 512) ? W[(size_t)k * NTOT + zcol]
                         : R[(size_t)(k - 512) * NTOT + zcol];
    }
    __half h[4];
    #pragma unroll
    for (int j = 0; j < 4; ++j) h[j] = __float2half(v[j]);
    ((uint2*)g_B)[(size_t)colp * 256 + threadIdx.x] = *(uint2*)h;
}

// -------- fused GEMM + gates --------
__global__ __launch_bounds__(256, 2)
void lstm_mma(const float* __restrict__ Cprev,
              const float* __restrict__ bias,
              float* __restrict__ out)
{
    extern __shared__ __align__(128) char smem[];
    const uint32_t sm = s2u(smem);
    const int tid = threadIdx.x, wid = tid >> 5, lane = tid & 31;
    const int warp_m = wid >> 2;            // 0..1  (64 rows)
    const int warp_n = wid & 3;             // 0..3  (32 cols)
    const int m0 = blockIdx.y * BM;
    const int n0 = blockIdx.x * BN;

    float acc[4][4][4];
    #pragma unroll
    for (int mi = 0; mi < 4; ++mi)
        #pragma unroll
        for (int ni = 0; ni < 4; ++ni)
            #pragma unroll
            for (int r = 0; r < 4; ++r) acc[mi][ni][r] = 0.0f;

    const int lr0 = tid >> 2, lseg = tid & 3;

    auto load_stage = [&](int t, int stg) {
        const uint32_t sb = sm + stg * STAGEB;
        const int kb = t * BK;
        #pragma unroll
        for (int j = 0; j < 2; ++j) {
            int r = lr0 + j * 64;
            uint32_t dst = sb + r * ROWB + lseg * 16;
            cp16(dst,         g_A + (size_t)(m0 + r) * KK + kb + lseg * 8);
            cp16(dst + TILEB, g_B + (size_t)(n0 + r) * KK + kb + lseg * 8);
        }
    };

    load_stage(0, 0); CP_COMMIT();
    load_stage(1, 1); CP_COMMIT();
    load_stage(2, 2); CP_COMMIT();

    const uint32_t aoff = (warp_m * 64 + (lane & 15)) * ROWB + ((lane >> 4) << 4);
    const uint32_t boff = TILEB
        + (warp_n * 32 + (lane & 7) + ((lane & 16) >> 1)) * ROWB + ((lane & 8) << 1);

    for (int t = 0; t < KT; ++t) {
        CP_WAIT2();
        __syncthreads();

        const uint32_t sb = sm + (t & 3) * STAGEB;
        #pragma unroll
        for (int ks = 0; ks < 2; ++ks) {
            const uint32_t kB = ks * 32;
            uint32_t ah[4][4], bh[2][4];
            #pragma unroll
            for (int mi = 0; mi < 4; ++mi)
                ldsm4(ah[mi], sb + aoff + mi * (16 * ROWB) + kB);
            #pragma unroll
            for (int nj = 0; nj < 2; ++nj)
                ldsm4(bh[nj], sb + boff + nj * (16 * ROWB) + kB);

            #pragma unroll
            for (int mi = 0; mi < 4; ++mi)
                #pragma unroll
                for (int ni = 0; ni < 4; ++ni)
                    mma16816(acc[mi][ni], ah[mi], &bh[ni >> 1][(ni & 1) * 2]);
        }

        if (t + 3 < KT) load_stage(t + 3, (t + 3) & 3);
        CP_COMMIT();
    }

    // ---- epilogue: stage z through smem (operand buffers dead) ----
    __syncthreads();
    float* zs = (float*)smem;               // [128][132]
    const int g = lane >> 2, c2 = (lane & 3) * 2;
    #pragma unroll
    for (int mi = 0; mi < 4; ++mi) {
        const int r0 = warp_m * 64 + mi * 16 + g;
        #pragma unroll
        for (int ni = 0; ni < 4; ++ni) {
            const int col = warp_n * 32 + ni * 8 + c2;
            zs[r0 * 132 + col]           = acc[mi][ni][0];
            zs[r0 * 132 + col + 1]       = acc[mi][ni][1];
            zs[(r0 + 8) * 132 + col]     = acc[mi][ni][2];
            zs[(r0 + 8) * 132 + col + 1] = acc[mi][ni][3];
        }
    }
    __syncthreads();

    const size_t BU = (size_t)MB * UU;
    #pragma unroll
    for (int i = 0; i < 16; ++i) {
        int q   = tid + i * 256;            // 0..4095
        int row = q >> 5;
        int ul  = q & 31;
        float4 zq = *(float4*)&zs[row * 132 + ul * 4];
        int u = blockIdx.x * 32 + ul;
        float zi = zq.x + __ldg(bias + u);
        float zf = zq.y + __ldg(bias + 512 + u);
        float zg = zq.z + __ldg(bias + 1024 + u);
        float zo = zq.w + __ldg(bias + 1536 + u);
        float cp = Cprev[(size_t)(m0 + row) * UU + u];
        float cn = sigf(zf) * cp + sigf(zi) * tanhf_fast(zg);
        float hv = sigf(zo) * tanhf_fast(cn);
        size_t o = (size_t)(m0 + row) * UU + u;
        out[o]          = hv;
        out[o + BU]     = hv;
        out[o + 2 * BU] = cn;
    }
}

// -------- launch --------
extern "C" void kernel_launch(void* const* d_in, const int* in_sizes, int n_in,
                              void* d_out, int out_size)
{
    const float* X    = (const float*)d_in[0];
    const float* H    = (const float*)d_in[1];
    const float* C    = (const float*)d_in[2];
    const float* W    = (const float*)d_in[3];
    const float* R    = (const float*)d_in[4];
    const float* bias = (const float*)d_in[5];
    float* out = (float*)d_out;

    static bool attr_done = false;
    if (!attr_done) {
        cudaFuncSetAttribute(lstm_mma,
                             cudaFuncAttributeMaxDynamicSharedMemorySize, SMEM_DYN);
        attr_done = true;
    }

    conv_a<<<MB * KK / 8 / 256, 256>>>(X, H);
    conv_b<<<NTOT, 256>>>(W, R);

    dim3 grid(NTOT / BN, MB / BM);          // (16, 64)
    lstm_mma<<<grid, 256, SMEM_DYN>>>(C, bias, out);
}